// round 14
// baseline (speedup 1.0000x reference)
#include <cuda_runtime.h>

#define NP 8192
#define NT 8192
#define CAP 256
#define ROW_F4 (NT/4)
#define FULLM 0xffffffffu
#define HALFN 4096            // node B = node A + HALFN

// ---------------- static scratch ----------------
__device__ __align__(16) float d_pa[NP * 64];
__device__ __align__(16) float d_pb[NP * 64];
__device__ __align__(16) float d_ta[NT * 64];
__device__ __align__(16) float d_tb[NT * 64];
__device__ __align__(16) float d_prp[NT * 16];   // t3 @ wp4_agg (for p-side L4)
__device__ __align__(16) float d_prt[NP * 16];   // p3 @ wt4_agg (for t-side L4)
__device__ float d_lp[NP];
__device__ float d_logits[NT];
__device__ int d_rcnt[NP];
__device__ int d_ccnt[NT];      // zero-init; re-zeroed by softmax kernel each launch
__device__ int d_rlist[NP * CAP];
__device__ int d_clist[NT * CAP];

// padded C=64,OUT=16 weight layout (conflict-free two k-halves)
#define W64X16(k, c) ((k) * 17 + (((k) >> 5) << 4) + (c))
// padded C=64,OUT=16 projection layout
#define WA64X16(k, c) ((k) * 16 + (((k) >> 5) << 4) + (c))

// ---------------- build: block per row + fused p-side L1 ----------------
// Streams the row, emits edges, accumulates agg_t = sum t0[j] in registers,
// and computes p1[row] = relu([p0|agg_t] @ Wp1 + b) in the epilogue.
__global__ void __launch_bounds__(256) build_k(
    const float* __restrict__ adj, const float* __restrict__ p0,
    const float* __restrict__ t0,
    const float* __restrict__ wp1, const float* __restrict__ bp1)
{
    __shared__ int s_cnt;
    __shared__ float s_agg[8];
    int row = blockIdx.x;
    int tid = threadIdx.x;
    if (tid == 0) s_cnt = 0;
    if (tid < 8) s_agg[tid] = 0.f;
    __syncthreads();

    const float4* a4 = reinterpret_cast<const float4*>(adj) + (size_t)row * ROW_F4 + tid;
    float4 v[8];
#pragma unroll
    for (int k = 0; k < 8; k++) v[k] = __ldcs(a4 + k * 256);

    float aggt[8] = {0.f, 0.f, 0.f, 0.f, 0.f, 0.f, 0.f, 0.f};
    bool has = false;

#pragma unroll
    for (int k = 0; k < 8; k++) {
        if (v[k].x != 0.f || v[k].y != 0.f || v[k].z != 0.f || v[k].w != 0.f) {
            int jb = (tid + k * 256) << 2;
            float vals[4] = {v[k].x, v[k].y, v[k].z, v[k].w};
#pragma unroll
            for (int q = 0; q < 4; q++) {
                if (vals[q] != 0.f) {
                    int j = jb + q;
                    int slot = atomicAdd(&s_cnt, 1);
                    if (slot < CAP) d_rlist[row * CAP + slot] = j;
                    int cs = atomicAdd(&d_ccnt[j], 1);
                    if (cs < CAP) d_clist[j * CAP + cs] = row;
                    // accumulate t0[j] (8 floats) into private registers
                    float4 f0 = *reinterpret_cast<const float4*>(t0 + j * 8);
                    float4 f1 = *reinterpret_cast<const float4*>(t0 + j * 8 + 4);
                    aggt[0] += f0.x; aggt[1] += f0.y; aggt[2] += f0.z; aggt[3] += f0.w;
                    aggt[4] += f1.x; aggt[5] += f1.y; aggt[6] += f1.z; aggt[7] += f1.w;
                    has = true;
                }
            }
        }
    }
    if (has) {
#pragma unroll
        for (int d = 0; d < 8; d++) atomicAdd(&s_agg[d], aggt[d]);
    }
    __syncthreads();
    if (tid == 0) d_rcnt[row] = min(s_cnt, CAP);

    // warp 0: p1[row] = relu([p0(8) | agg_t(8)] @ Wp1(16x8) + b)
    if (tid < 32) {
        int c = tid & 7, kg = tid >> 3;     // 8 cols x 4 k-groups
        float acc = 0.f;
#pragma unroll
        for (int kk = 0; kk < 4; kk++) {
            int k = kg * 4 + kk;
            float xv = (k < 8) ? __ldg(p0 + row * 8 + k) : s_agg[k - 8];
            acc += xv * __ldg(wp1 + k * 8 + c);
        }
        acc += __shfl_down_sync(FULLM, acc, 8);
        acc += __shfl_down_sync(FULLM, acc, 16);
        if (tid < 8) d_pa[row * 8 + tid] = fmaxf(acc + __ldg(bp1 + tid), 0.f);
    }
}

// ---------------- shfl-based neighbor index fetch (e < 64) ----------------
__device__ __forceinline__ int shfl_idx(int e, int i0, int i1) {
    int v = (e & 32) ? i1 : i0;
    return __shfl_sync(FULLM, v, e & 31);
}
__device__ __forceinline__ void add4(float4& a, const float* p) {
    float4 t = *reinterpret_cast<const float4*>(p);
    a.x += t.x; a.y += t.y; a.z += t.z; a.w += t.w;
}

// ---------------- dual-node gather: 4 independent load chains per iteration ----------------
template <int IN>
__device__ __forceinline__ void gather_agg2(
    const float* __restrict__ feat,
    const int* __restrict__ lstA, int nA,
    const int* __restrict__ lstB, int nB,
    int lane, float4& outA, float4& outB,
    int& iA0, int& iA1, int& iB0, int& iB1)
{
    constexpr int V = IN / 4;
    constexpr int G = 32 / V;
    int v = lane % V, g = lane / V;
    iA0 = (lane < nA) ? lstA[lane] : 0;
    iA1 = (lane + 32 < nA) ? lstA[lane + 32] : 0;
    iB0 = (lane < nB) ? lstB[lane] : 0;
    iB1 = (lane + 32 < nB) ? lstB[lane + 32] : 0;
    int nlA = min(nA, 64), nlB = min(nB, 64);
    int iters = (max(nlA, nlB) + G - 1) / G;       // warp-uniform
    float4 a0 = make_float4(0.f, 0.f, 0.f, 0.f);
    float4 a1 = make_float4(0.f, 0.f, 0.f, 0.f);
    float4 b0 = make_float4(0.f, 0.f, 0.f, 0.f);
    float4 b1 = make_float4(0.f, 0.f, 0.f, 0.f);
    int k = 0;
    for (; k + 1 < iters; k += 2) {
        int e0 = g + k * G, e1 = e0 + G;
        int xA0 = shfl_idx(e0, iA0, iA1);
        int xA1 = shfl_idx(e1, iA0, iA1);
        int xB0 = shfl_idx(e0, iB0, iB1);
        int xB1 = shfl_idx(e1, iB0, iB1);
        if (e0 < nlA) add4(a0, feat + xA0 * IN + v * 4);
        if (e1 < nlA) add4(a1, feat + xA1 * IN + v * 4);
        if (e0 < nlB) add4(b0, feat + xB0 * IN + v * 4);
        if (e1 < nlB) add4(b1, feat + xB1 * IN + v * 4);
    }
    if (k < iters) {
        int e0 = g + k * G;
        int xA0 = shfl_idx(e0, iA0, iA1);
        int xB0 = shfl_idx(e0, iB0, iB1);
        if (e0 < nlA) add4(a0, feat + xA0 * IN + v * 4);
        if (e0 < nlB) add4(b0, feat + xB0 * IN + v * 4);
    }
    if (nA > 64) {                                  // rare tails (warp-uniform predicates)
        for (int e = 64 + g; __any_sync(FULLM, e < nA); e += G)
            if (e < nA) add4(a0, feat + lstA[e] * IN + v * 4);
    }
    if (nB > 64) {
        for (int e = 64 + g; __any_sync(FULLM, e < nB); e += G)
            if (e < nB) add4(b0, feat + lstB[e] * IN + v * 4);
    }
    a0.x += a1.x; a0.y += a1.y; a0.z += a1.z; a0.w += a1.w;
    b0.x += b1.x; b0.y += b1.y; b0.z += b1.z; b0.w += b1.w;
#pragma unroll
    for (int d = G / 2; d > 0; d >>= 1) {
        a0.x += __shfl_down_sync(FULLM, a0.x, d * V);
        a0.y += __shfl_down_sync(FULLM, a0.y, d * V);
        a0.z += __shfl_down_sync(FULLM, a0.z, d * V);
        a0.w += __shfl_down_sync(FULLM, a0.w, d * V);
        b0.x += __shfl_down_sync(FULLM, b0.x, d * V);
        b0.y += __shfl_down_sync(FULLM, b0.y, d * V);
        b0.z += __shfl_down_sync(FULLM, b0.z, d * V);
        b0.w += __shfl_down_sync(FULLM, b0.w, d * V);
    }
    outA = a0; outB = b0;
}

// ---------------- k-split column GEMM (padded stride OUT+2) ----------------
template <int C, int OUT>
__device__ __forceinline__ float gemm_kcol(const float* xs, const float* sW, int lane) {
    constexpr int SPLIT = 32 / OUT;
    constexpr int KP = C / SPLIT;
    int col = lane & (OUT - 1);
    int grp = lane / OUT;
    int k0 = grp * KP;
    float acc = 0.f;
#pragma unroll
    for (int k = 0; k < KP; k += 4) {
        float4 xv = *reinterpret_cast<const float4*>(xs + k0 + k);
        acc += xv.x * sW[(k0 + k)     * (OUT + 2) + col];
        acc += xv.y * sW[(k0 + k + 1) * (OUT + 2) + col];
        acc += xv.z * sW[(k0 + k + 2) * (OUT + 2) + col];
        acc += xv.w * sW[(k0 + k + 3) * (OUT + 2) + col];
    }
#pragma unroll
    for (int d = OUT; d < 32; d <<= 1) acc += __shfl_down_sync(FULLM, acc, d);
    return acc;
}

// ---------------- dual-node generic layer (OUT <= 32) ----------------
template <int IN, int OUT, bool SELF_FIRST>
__device__ __forceinline__ void layer_node2(
    int nodeA, int nodeB, const float* __restrict__ self_f, const float* __restrict__ other_f,
    const int* __restrict__ cnt, const int* __restrict__ list,
    const float* sW, const float* sB, float* __restrict__ out_f,
    float* xsA, float* xsB, int lane)
{
    constexpr int C = 2 * IN;
    constexpr int SOFF = SELF_FIRST ? 0 : IN;
    constexpr int AOFF = SELF_FIRST ? IN : 0;
#pragma unroll
    for (int k = lane; k < IN; k += 32) {
        xsA[SOFF + k] = self_f[nodeA * IN + k];
        xsB[SOFF + k] = self_f[nodeB * IN + k];
    }
    int nA = min(cnt[nodeA], CAP), nB = min(cnt[nodeB], CAP);
    const int* lstA = list + nodeA * CAP;
    const int* lstB = list + nodeB * CAP;
    float4 accA, accB; int iA0, iA1, iB0, iB1;
    gather_agg2<IN>(other_f, lstA, nA, lstB, nB, lane, accA, accB, iA0, iA1, iB0, iB1);
    constexpr int V = IN / 4;
    int v = lane % V, g = lane / V;
    if (g == 0) {
        *reinterpret_cast<float4*>(xsA + AOFF + v * 4) = accA;
        *reinterpret_cast<float4*>(xsB + AOFF + v * 4) = accB;
    }
    __syncwarp();
    float aA = gemm_kcol<C, OUT>(xsA, sW, lane);
    float aB = gemm_kcol<C, OUT>(xsB, sW, lane);
    if (lane < OUT) {
        out_f[nodeA * OUT + lane] = fmaxf(aA + sB[lane], 0.f);
        out_f[nodeB * OUT + lane] = fmaxf(aB + sB[lane], 0.f);
    }
    __syncwarp();
}

// ---------------- T1: t-side of layer 1 only (p-side folded into build) ----------------
__global__ void __launch_bounds__(256) t1_k(
    const float* __restrict__ t0, const float* __restrict__ p0,
    const float* __restrict__ wt, const float* __restrict__ bt)
{
    __shared__ float sW[16 * 10], sB[8];
    __shared__ __align__(16) float sX[8][2][16];
    int tid = threadIdx.x, warp = tid >> 5, lane = tid & 31;
    if (tid < 128) sW[(tid >> 3) * 10 + (tid & 7)] = wt[tid];
    if (tid < 8) sB[tid] = bt[tid];
    __syncthreads();
    int gw = blockIdx.x * 8 + warp;
    layer_node2<8, 8, false>(gw, gw + HALFN, t0, p0, d_ccnt, d_clist, sW, sB, d_ta, sX[warp][0], sX[warp][1], lane);
}

// ---------------- L2 ----------------
__global__ void __launch_bounds__(256) l2_k(
    const float* __restrict__ wp, const float* __restrict__ bp,
    const float* __restrict__ wt, const float* __restrict__ bt)
{
    __shared__ float sW[16 * 18], sB[16];
    __shared__ __align__(16) float sX[8][2][16];
    int tid = threadIdx.x, warp = tid >> 5, lane = tid & 31;
    int half = gridDim.x >> 1;
    bool pside = blockIdx.x < half;
    const float* W = pside ? wp : wt;
    const float* B = pside ? bp : bt;
    if (tid < 256) sW[(tid >> 4) * 18 + (tid & 15)] = W[tid];
    if (tid < 16) sB[tid] = B[tid];
    __syncthreads();
    int bid = pside ? blockIdx.x : blockIdx.x - half;
    int gw = bid * 8 + warp;
    if (pside) layer_node2<8, 16, true >(gw, gw + HALFN, d_pa, d_ta, d_rcnt, d_rlist, sW, sB, d_pb, sX[warp][0], sX[warp][1], lane);
    else       layer_node2<8, 16, false>(gw, gw + HALFN, d_ta, d_pa, d_ccnt, d_clist, sW, sB, d_tb, sX[warp][0], sX[warp][1], lane);
}

// ---------------- L3 per-node GEMM + projection ----------------
__device__ __forceinline__ void l3_math(
    int node, const float* sW, const float* sB, const float* sWA,
    float* __restrict__ out_f, float* __restrict__ proj_f, float* xs, int lane)
{
    constexpr int OUT = 64;
    float2 acc = *reinterpret_cast<const float2*>(sB + 2 * lane);
#pragma unroll
    for (int k = 0; k < 32; k += 4) {
        float4 xv = *reinterpret_cast<const float4*>(xs + k);
        float2 w;
        w = *reinterpret_cast<const float2*>(sW + (k    ) * OUT + 2 * lane); acc.x += xv.x * w.x; acc.y += xv.x * w.y;
        w = *reinterpret_cast<const float2*>(sW + (k + 1) * OUT + 2 * lane); acc.x += xv.y * w.x; acc.y += xv.y * w.y;
        w = *reinterpret_cast<const float2*>(sW + (k + 2) * OUT + 2 * lane); acc.x += xv.z * w.x; acc.y += xv.z * w.y;
        w = *reinterpret_cast<const float2*>(sW + (k + 3) * OUT + 2 * lane); acc.x += xv.w * w.x; acc.y += xv.w * w.y;
    }
    acc.x = fmaxf(acc.x, 0.f); acc.y = fmaxf(acc.y, 0.f);
    *reinterpret_cast<float2*>(out_f + node * OUT + 2 * lane) = acc;
    *reinterpret_cast<float2*>(xs + 64 + 2 * lane) = acc;
    __syncwarp();
    int c = lane & 15, h = lane >> 4;
    float pr = 0.f;
#pragma unroll
    for (int k = 0; k < 32; k += 4) {
        int kk = h * 32 + k;
        float4 xv = *reinterpret_cast<const float4*>(xs + 64 + kk);
        pr += xv.x * sWA[WA64X16(kk,     c)];
        pr += xv.y * sWA[WA64X16(kk + 1, c)];
        pr += xv.z * sWA[WA64X16(kk + 2, c)];
        pr += xv.w * sWA[WA64X16(kk + 3, c)];
    }
    pr += __shfl_down_sync(FULLM, pr, 16);
    if (lane < 16) proj_f[node * 16 + lane] = pr;
    __syncwarp();
}

template <bool SELF_FIRST>
__device__ __forceinline__ void layer3_node2(
    int nodeA, int nodeB, const float* __restrict__ self_f, const float* __restrict__ other_f,
    const int* __restrict__ cnt, const int* __restrict__ list,
    const float* sW, const float* sB, const float* sWA,
    float* __restrict__ out_f, float* __restrict__ proj_f,
    float* xsA, float* xsB, int lane)
{
    constexpr int IN = 16;
    constexpr int SOFF = SELF_FIRST ? 0 : IN;
    constexpr int AOFF = SELF_FIRST ? IN : 0;
#pragma unroll
    for (int k = lane; k < IN; k += 32) {
        xsA[SOFF + k] = self_f[nodeA * IN + k];
        xsB[SOFF + k] = self_f[nodeB * IN + k];
    }
    int nA = min(cnt[nodeA], CAP), nB = min(cnt[nodeB], CAP);
    float4 accA, accB; int iA0, iA1, iB0, iB1;
    gather_agg2<16>(other_f, list + nodeA * CAP, nA, list + nodeB * CAP, nB,
                    lane, accA, accB, iA0, iA1, iB0, iB1);
    int v = lane & 3, g = lane >> 2;
    if (g == 0) {
        *reinterpret_cast<float4*>(xsA + AOFF + v * 4) = accA;
        *reinterpret_cast<float4*>(xsB + AOFF + v * 4) = accB;
    }
    __syncwarp();
    l3_math(nodeA, sW, sB, sWA, out_f, proj_f, xsA, lane);
    l3_math(nodeB, sW, sB, sWA, out_f, proj_f, xsB, lane);
}

__global__ void __launch_bounds__(256, 5) l3_k(
    const float* __restrict__ wp3, const float* __restrict__ bp3,
    const float* __restrict__ wt3, const float* __restrict__ bt3,
    const float* __restrict__ wp4, const float* __restrict__ wt4)
{
    __shared__ float sW[2048], sWA[1040], sB[64];
    __shared__ __align__(16) float sX[8][2][128];
    int tid = threadIdx.x, warp = tid >> 5, lane = tid & 31;
    int half = gridDim.x >> 1;
    bool pside = blockIdx.x < half;
    const float* W  = pside ? wp3 : wt3;
    const float* B  = pside ? bp3 : bt3;
    const float* WA = pside ? wt4 : (wp4 + 1024);
    ((float4*)sW)[tid]       = ((const float4*)W)[tid];
    ((float4*)sW)[tid + 256] = ((const float4*)W)[tid + 256];
    for (int i = tid; i < 1024; i += 256) {
        int k = i >> 4, c = i & 15;
        sWA[WA64X16(k, c)] = WA[i];
    }
    if (tid < 64) sB[tid] = B[tid];
    __syncthreads();
    int bid = pside ? blockIdx.x : blockIdx.x - half;
    int gw = bid * 8 + warp;
    if (pside) layer3_node2<true >(gw, gw + HALFN, d_pb, d_tb, d_rcnt, d_rlist, sW, sB, sWA, d_pa, d_prt, sX[warp][0], sX[warp][1], lane);
    else       layer3_node2<false>(gw, gw + HALFN, d_tb, d_pb, d_ccnt, d_clist, sW, sB, sWA, d_ta, d_prp, sX[warp][0], sX[warp][1], lane);
}

// ---------------- L4 per-node math (xs: self in [0,64), agg in [64,80)) ----------------
__device__ __forceinline__ float l4_math(
    const float* sW, const float* sB, const float* sAC, float* xs, int lane)
{
    int c = lane & 15, h = lane >> 4;
    float acc = 0.f;
#pragma unroll
    for (int k = 0; k < 32; k += 4) {
        int kk = h * 32 + k;
        float4 xv = *reinterpret_cast<const float4*>(xs + kk);
        acc += xv.x * sW[W64X16(kk,     c)];
        acc += xv.y * sW[W64X16(kk + 1, c)];
        acc += xv.z * sW[W64X16(kk + 2, c)];
        acc += xv.w * sW[W64X16(kk + 3, c)];
    }
    acc += __shfl_down_sync(FULLM, acc, 16);
    float contrib = 0.f;
    if (lane < 16) {
        float a = sB[lane] + xs[64 + lane] + acc;
        contrib = fmaxf(a, 0.f) * sAC[lane];
    }
#pragma unroll
    for (int d = 16; d > 0; d >>= 1)
        contrib += __shfl_down_sync(FULLM, contrib, d);
    return contrib;   // lane 0
}

__device__ __forceinline__ void l4_front2(
    int nodeA, int nodeB, const float* __restrict__ self_f, const float* __restrict__ proj_other,
    const int* __restrict__ cnt, const int* __restrict__ list,
    float* xsA, float* xsB, int lane,
    int& nA, int& nB, int& iA0, int& iA1, int& iB0, int& iB1)
{
#pragma unroll
    for (int k = lane; k < 64; k += 32) {
        xsA[k] = self_f[nodeA * 64 + k];
        xsB[k] = self_f[nodeB * 64 + k];
    }
    nA = min(cnt[nodeA], CAP); nB = min(cnt[nodeB], CAP);
    float4 accA, accB;
    gather_agg2<16>(proj_other, list + nodeA * CAP, nA, list + nodeB * CAP, nB,
                    lane, accA, accB, iA0, iA1, iB0, iB1);
    int v = lane & 3, g = lane >> 2;
    if (g == 0) {
        *reinterpret_cast<float4*>(xsA + 64 + v * 4) = accA;
        *reinterpret_cast<float4*>(xsB + 64 + v * 4) = accB;
    }
    __syncwarp();
}

// ---------------- L4 p-side ----------------
__global__ void __launch_bounds__(256, 5) l4p_k(
    const float* __restrict__ wp4, const float* __restrict__ bp4,
    const float* __restrict__ wac)
{
    __shared__ float sW[1104], sB[16], sAC[16];
    __shared__ __align__(16) float sX[8][2][80];
    int tid = threadIdx.x, warp = tid >> 5, lane = tid & 31;
    for (int i = tid; i < 1024; i += 256) {
        int k = i >> 4, c = i & 15;
        sW[W64X16(k, c)] = wp4[i];
    }
    if (tid < 16) { sB[tid] = bp4[tid]; sAC[tid] = wac[tid]; }
    __syncthreads();
    int gw = blockIdx.x * 8 + warp;
    int nodeA = gw, nodeB = gw + HALFN;
    int nA, nB, iA0, iA1, iB0, iB1;
    l4_front2(nodeA, nodeB, d_pa, d_prp, d_rcnt, d_rlist, sX[warp][0], sX[warp][1], lane, nA, nB, iA0, iA1, iB0, iB1);
    float cA = l4_math(sW, sB, sAC, sX[warp][0], lane);
    float cB = l4_math(sW, sB, sAC, sX[warp][1], lane);
    if (lane == 0) { d_lp[nodeA] = cA; d_lp[nodeB] = cB; }
}

// ---------------- L4 t-side + logits ----------------
__global__ void __launch_bounds__(256, 5) l4t_logits_k(
    const float* __restrict__ wt4, const float* __restrict__ bt4,
    const float* __restrict__ wac, const float* __restrict__ bac)
{
    __shared__ float sW[1104], sB[16], sAC[16];
    __shared__ __align__(16) float sX[8][2][80];
    int tid = threadIdx.x, warp = tid >> 5, lane = tid & 31;
    for (int i = tid; i < 1024; i += 256) {
        int k = i >> 4, c = i & 15;
        sW[W64X16(k, c)] = wt4[1024 + i];   // self part (rows 64..127)
    }
    if (tid < 16) { sB[tid] = bt4[tid]; sAC[tid] = wac[16 + tid]; }
    __syncthreads();
    float bias = bac[0];
    int gw = blockIdx.x * 8 + warp;
    int nodeA = gw, nodeB = gw + HALFN;
    int nA, nB, iA0, iA1, iB0, iB1;
    l4_front2(nodeA, nodeB, d_ta, d_prt, d_ccnt, d_clist, sX[warp][0], sX[warp][1], lane, nA, nB, iA0, iA1, iB0, iB1);

    float sA = 0.f, sBv = 0.f;
    if (lane < nA) sA += d_lp[iA0];
    if (lane + 32 < nA) sA += d_lp[iA1];
    if (lane < nB) sBv += d_lp[iB0];
    if (lane + 32 < nB) sBv += d_lp[iB1];
    if (nA > 64) {
        const int* lstA = d_clist + nodeA * CAP;
        for (int e = 64 + lane; __any_sync(FULLM, e < nA); e += 32)
            if (e < nA) sA += d_lp[lstA[e]];
    }
    if (nB > 64) {
        const int* lstB = d_clist + nodeB * CAP;
        for (int e = 64 + lane; __any_sync(FULLM, e < nB); e += 32)
            if (e < nB) sBv += d_lp[lstB[e]];
    }

    float cA = l4_math(sW, sB, sAC, sX[warp][0], lane);
    float cB = l4_math(sW, sB, sAC, sX[warp][1], lane);
#pragma unroll
    for (int d = 16; d > 0; d >>= 1) {
        sA  += __shfl_down_sync(FULLM, sA, d);
        sBv += __shfl_down_sync(FULLM, sBv, d);
    }
    if (lane == 0) {
        d_logits[nodeA] = sA + cA + bias;
        d_logits[nodeB] = sBv + cB + bias;
    }
}

// ---------------- softmax + ccnt reset ----------------
__global__ void __launch_bounds__(1024) softmax_k(float* __restrict__ out) {
    __shared__ float sm[1024];
    int tid = threadIdx.x;
    float m = -1e30f;
    for (int i = tid; i < NT; i += 1024) m = fmaxf(m, d_logits[i]);
    sm[tid] = m; __syncthreads();
    for (int s = 512; s > 0; s >>= 1) {
        if (tid < s) sm[tid] = fmaxf(sm[tid], sm[tid + s]);
        __syncthreads();
    }
    float mx = sm[0];
    __syncthreads();
    float s = 0.f;
    for (int i = tid; i < NT; i += 1024) s += __expf(d_logits[i] - mx);
    sm[tid] = s; __syncthreads();
    for (int st = 512; st > 0; st >>= 1) {
        if (tid < st) sm[tid] += sm[tid + st];
        __syncthreads();
    }
    float inv = 1.f / sm[0];
    for (int i = tid; i < NT; i += 1024) {
        out[i] = __expf(d_logits[i] - mx) * inv;
        d_ccnt[i] = 0;                    // reset for next launch
    }
}

// ---------------- launch ----------------
extern "C" void kernel_launch(void* const* d_in, const int* in_sizes, int n_in,
                              void* d_out, int out_size) {
    const float* p    = (const float*)d_in[0];
    const float* t    = (const float*)d_in[1];
    const float* adj  = (const float*)d_in[2];
    const float* w_p1 = (const float*)d_in[3];  const float* b_p1 = (const float*)d_in[4];
    const float* w_t1 = (const float*)d_in[5];  const float* b_t1 = (const float*)d_in[6];
    const float* w_p2 = (const float*)d_in[7];  const float* b_p2 = (const float*)d_in[8];
    const float* w_t2 = (const float*)d_in[9];  const float* b_t2 = (const float*)d_in[10];
    const float* w_p3 = (const float*)d_in[11]; const float* b_p3 = (const float*)d_in[12];
    const float* w_t3 = (const float*)d_in[13]; const float* b_t3 = (const float*)d_in[14];
    const float* w_p4 = (const float*)d_in[15]; const float* b_p4 = (const float*)d_in[16];
    const float* w_t4 = (const float*)d_in[17]; const float* b_t4 = (const float*)d_in[18];
    const float* w_ac = (const float*)d_in[19]; const float* b_ac = (const float*)d_in[20];
    float* out = (float*)d_out;

    build_k<<<NP, 256>>>(adj, p, t, w_p1, b_p1);         // edges + p-side L1
    t1_k<<<512, 256>>>(t, p, w_t1, b_t1);                // t-side L1
    l2_k<<<1024, 256>>>(w_p2, b_p2, w_t2, b_t2);
    l3_k<<<1024, 256>>>(w_p3, b_p3, w_t3, b_t3, w_p4, w_t4);
    l4p_k<<<512, 256>>>(w_p4, b_p4, w_ac);
    l4t_logits_k<<<512, 256>>>(w_t4, b_t4, w_ac, b_ac);
    softmax_k<<<1, 1024>>>(out);
}

// round 15
// speedup vs baseline: 2.4628x; 2.4628x over previous
#include <cuda_runtime.h>

#define NP 8192
#define NT 8192
#define CAP 256
#define ROW_F4 (NT/4)
#define FULLM 0xffffffffu
#define HALFN 4096            // node B = node A + HALFN

// ---------------- static scratch ----------------
__device__ __align__(16) float d_pa[NP * 64];
__device__ __align__(16) float d_pb[NP * 64];
__device__ __align__(16) float d_ta[NT * 64];
__device__ __align__(16) float d_tb[NT * 64];
__device__ __align__(16) float d_prp[NT * 16];   // t3 @ wp4_agg (for p-side L4)
__device__ __align__(16) float d_prt[NP * 16];   // p3 @ wt4_agg (for t-side L4)
__device__ float d_lp[NP];
__device__ float d_logits[NT];
__device__ int d_rcnt[NP];
__device__ int d_ccnt[NT];      // zero-init; re-zeroed by l4t_logits_k each launch
__device__ int d_rlist[NP * CAP];
__device__ int d_clist[NT * CAP];

// padded C=64,OUT=16 weight layout (conflict-free two k-halves)
#define W64X16(k, c) ((k) * 17 + (((k) >> 5) << 4) + (c))
// padded C=64,OUT=16 projection layout
#define WA64X16(k, c) ((k) * 16 + (((k) >> 5) << 4) + (c))

// ---------------- build: block per row, 8 in-flight float4 loads per thread ----------------
__global__ void __launch_bounds__(256) build_k(const float* __restrict__ adj) {
    __shared__ int s_cnt;
    int row = blockIdx.x;
    if (threadIdx.x == 0) s_cnt = 0;
    __syncthreads();

    const float4* a4 = reinterpret_cast<const float4*>(adj) + (size_t)row * ROW_F4 + threadIdx.x;
    float4 v[8];
#pragma unroll
    for (int k = 0; k < 8; k++) v[k] = __ldcs(a4 + k * 256);

#pragma unroll
    for (int k = 0; k < 8; k++) {
        if (v[k].x != 0.f || v[k].y != 0.f || v[k].z != 0.f || v[k].w != 0.f) {
            int jb = (threadIdx.x + k * 256) << 2;
            float vals[4] = {v[k].x, v[k].y, v[k].z, v[k].w};
#pragma unroll
            for (int q = 0; q < 4; q++) {
                if (vals[q] != 0.f) {
                    int j = jb + q;
                    int slot = atomicAdd(&s_cnt, 1);
                    if (slot < CAP) d_rlist[row * CAP + slot] = j;
                    int cs = atomicAdd(&d_ccnt[j], 1);
                    if (cs < CAP) d_clist[j * CAP + cs] = row;
                }
            }
        }
    }
    __syncthreads();
    if (threadIdx.x == 0) d_rcnt[row] = min(s_cnt, CAP);
}

// ---------------- shfl-based neighbor index fetch (e < 64) ----------------
__device__ __forceinline__ int shfl_idx(int e, int i0, int i1) {
    int v = (e & 32) ? i1 : i0;
    return __shfl_sync(FULLM, v, e & 31);
}
__device__ __forceinline__ void add4(float4& a, const float* p) {
    float4 t = *reinterpret_cast<const float4*>(p);
    a.x += t.x; a.y += t.y; a.z += t.z; a.w += t.w;
}

// ---------------- dual-node gather: 4 independent load chains per iteration ----------------
template <int IN>
__device__ __forceinline__ void gather_agg2(
    const float* __restrict__ feat,
    const int* __restrict__ lstA, int nA,
    const int* __restrict__ lstB, int nB,
    int lane, float4& outA, float4& outB,
    int& iA0, int& iA1, int& iB0, int& iB1)
{
    constexpr int V = IN / 4;
    constexpr int G = 32 / V;
    int v = lane % V, g = lane / V;
    iA0 = (lane < nA) ? lstA[lane] : 0;
    iA1 = (lane + 32 < nA) ? lstA[lane + 32] : 0;
    iB0 = (lane < nB) ? lstB[lane] : 0;
    iB1 = (lane + 32 < nB) ? lstB[lane + 32] : 0;
    int nlA = min(nA, 64), nlB = min(nB, 64);
    int iters = (max(nlA, nlB) + G - 1) / G;       // warp-uniform
    float4 a0 = make_float4(0.f, 0.f, 0.f, 0.f);
    float4 a1 = make_float4(0.f, 0.f, 0.f, 0.f);
    float4 b0 = make_float4(0.f, 0.f, 0.f, 0.f);
    float4 b1 = make_float4(0.f, 0.f, 0.f, 0.f);
    int k = 0;
    for (; k + 1 < iters; k += 2) {
        int e0 = g + k * G, e1 = e0 + G;
        int xA0 = shfl_idx(e0, iA0, iA1);
        int xA1 = shfl_idx(e1, iA0, iA1);
        int xB0 = shfl_idx(e0, iB0, iB1);
        int xB1 = shfl_idx(e1, iB0, iB1);
        if (e0 < nlA) add4(a0, feat + xA0 * IN + v * 4);
        if (e1 < nlA) add4(a1, feat + xA1 * IN + v * 4);
        if (e0 < nlB) add4(b0, feat + xB0 * IN + v * 4);
        if (e1 < nlB) add4(b1, feat + xB1 * IN + v * 4);
    }
    if (k < iters) {
        int e0 = g + k * G;
        int xA0 = shfl_idx(e0, iA0, iA1);
        int xB0 = shfl_idx(e0, iB0, iB1);
        if (e0 < nlA) add4(a0, feat + xA0 * IN + v * 4);
        if (e0 < nlB) add4(b0, feat + xB0 * IN + v * 4);
    }
    if (nA > 64) {                                  // rare tails (warp-uniform predicates)
        for (int e = 64 + g; __any_sync(FULLM, e < nA); e += G)
            if (e < nA) add4(a0, feat + lstA[e] * IN + v * 4);
    }
    if (nB > 64) {
        for (int e = 64 + g; __any_sync(FULLM, e < nB); e += G)
            if (e < nB) add4(b0, feat + lstB[e] * IN + v * 4);
    }
    a0.x += a1.x; a0.y += a1.y; a0.z += a1.z; a0.w += a1.w;
    b0.x += b1.x; b0.y += b1.y; b0.z += b1.z; b0.w += b1.w;
#pragma unroll
    for (int d = G / 2; d > 0; d >>= 1) {
        a0.x += __shfl_down_sync(FULLM, a0.x, d * V);
        a0.y += __shfl_down_sync(FULLM, a0.y, d * V);
        a0.z += __shfl_down_sync(FULLM, a0.z, d * V);
        a0.w += __shfl_down_sync(FULLM, a0.w, d * V);
        b0.x += __shfl_down_sync(FULLM, b0.x, d * V);
        b0.y += __shfl_down_sync(FULLM, b0.y, d * V);
        b0.z += __shfl_down_sync(FULLM, b0.z, d * V);
        b0.w += __shfl_down_sync(FULLM, b0.w, d * V);
    }
    outA = a0; outB = b0;
}

// ---------------- k-split column GEMM (padded stride OUT+2) ----------------
template <int C, int OUT>
__device__ __forceinline__ float gemm_kcol(const float* xs, const float* sW, int lane) {
    constexpr int SPLIT = 32 / OUT;
    constexpr int KP = C / SPLIT;
    int col = lane & (OUT - 1);
    int grp = lane / OUT;
    int k0 = grp * KP;
    float acc = 0.f;
#pragma unroll
    for (int k = 0; k < KP; k += 4) {
        float4 xv = *reinterpret_cast<const float4*>(xs + k0 + k);
        acc += xv.x * sW[(k0 + k)     * (OUT + 2) + col];
        acc += xv.y * sW[(k0 + k + 1) * (OUT + 2) + col];
        acc += xv.z * sW[(k0 + k + 2) * (OUT + 2) + col];
        acc += xv.w * sW[(k0 + k + 3) * (OUT + 2) + col];
    }
#pragma unroll
    for (int d = OUT; d < 32; d <<= 1) acc += __shfl_down_sync(FULLM, acc, d);
    return acc;
}

// ---------------- dual-node generic layer (OUT <= 32) ----------------
template <int IN, int OUT, bool SELF_FIRST>
__device__ __forceinline__ void layer_node2(
    int nodeA, int nodeB, const float* __restrict__ self_f, const float* __restrict__ other_f,
    const int* __restrict__ cnt, const int* __restrict__ list,
    const float* sW, const float* sB, float* __restrict__ out_f,
    float* xsA, float* xsB, int lane)
{
    constexpr int C = 2 * IN;
    constexpr int SOFF = SELF_FIRST ? 0 : IN;
    constexpr int AOFF = SELF_FIRST ? IN : 0;
#pragma unroll
    for (int k = lane; k < IN; k += 32) {
        xsA[SOFF + k] = self_f[nodeA * IN + k];
        xsB[SOFF + k] = self_f[nodeB * IN + k];
    }
    int nA = min(cnt[nodeA], CAP), nB = min(cnt[nodeB], CAP);
    const int* lstA = list + nodeA * CAP;
    const int* lstB = list + nodeB * CAP;
    float4 accA, accB; int iA0, iA1, iB0, iB1;
    gather_agg2<IN>(other_f, lstA, nA, lstB, nB, lane, accA, accB, iA0, iA1, iB0, iB1);
    constexpr int V = IN / 4;
    int v = lane % V, g = lane / V;
    if (g == 0) {
        *reinterpret_cast<float4*>(xsA + AOFF + v * 4) = accA;
        *reinterpret_cast<float4*>(xsB + AOFF + v * 4) = accB;
    }
    __syncwarp();
    float aA = gemm_kcol<C, OUT>(xsA, sW, lane);
    float aB = gemm_kcol<C, OUT>(xsB, sW, lane);
    if (lane < OUT) {
        out_f[nodeA * OUT + lane] = fmaxf(aA + sB[lane], 0.f);
        out_f[nodeB * OUT + lane] = fmaxf(aB + sB[lane], 0.f);
    }
    __syncwarp();
}

// ---------------- L1 ----------------
__global__ void __launch_bounds__(256) l1_k(
    const float* __restrict__ p0, const float* __restrict__ t0,
    const float* __restrict__ wp, const float* __restrict__ bp,
    const float* __restrict__ wt, const float* __restrict__ bt)
{
    __shared__ float sW[16 * 10], sB[8];
    __shared__ __align__(16) float sX[8][2][16];
    int tid = threadIdx.x, warp = tid >> 5, lane = tid & 31;
    int half = gridDim.x >> 1;
    bool pside = blockIdx.x < half;
    const float* W = pside ? wp : wt;
    const float* B = pside ? bp : bt;
    if (tid < 128) sW[(tid >> 3) * 10 + (tid & 7)] = W[tid];
    if (tid < 8) sB[tid] = B[tid];
    __syncthreads();
    int bid = pside ? blockIdx.x : blockIdx.x - half;
    int gw = bid * 8 + warp;
    if (pside) layer_node2<8, 8, true >(gw, gw + HALFN, p0, t0, d_rcnt, d_rlist, sW, sB, d_pa, sX[warp][0], sX[warp][1], lane);
    else       layer_node2<8, 8, false>(gw, gw + HALFN, t0, p0, d_ccnt, d_clist, sW, sB, d_ta, sX[warp][0], sX[warp][1], lane);
}

// ---------------- L2 ----------------
__global__ void __launch_bounds__(256) l2_k(
    const float* __restrict__ wp, const float* __restrict__ bp,
    const float* __restrict__ wt, const float* __restrict__ bt)
{
    __shared__ float sW[16 * 18], sB[16];
    __shared__ __align__(16) float sX[8][2][16];
    int tid = threadIdx.x, warp = tid >> 5, lane = tid & 31;
    int half = gridDim.x >> 1;
    bool pside = blockIdx.x < half;
    const float* W = pside ? wp : wt;
    const float* B = pside ? bp : bt;
    if (tid < 256) sW[(tid >> 4) * 18 + (tid & 15)] = W[tid];
    if (tid < 16) sB[tid] = B[tid];
    __syncthreads();
    int bid = pside ? blockIdx.x : blockIdx.x - half;
    int gw = bid * 8 + warp;
    if (pside) layer_node2<8, 16, true >(gw, gw + HALFN, d_pa, d_ta, d_rcnt, d_rlist, sW, sB, d_pb, sX[warp][0], sX[warp][1], lane);
    else       layer_node2<8, 16, false>(gw, gw + HALFN, d_ta, d_pa, d_ccnt, d_clist, sW, sB, d_tb, sX[warp][0], sX[warp][1], lane);
}

// ---------------- L3 per-node GEMM + projection ----------------
__device__ __forceinline__ void l3_math(
    int node, const float* sW, const float* sB, const float* sWA,
    float* __restrict__ out_f, float* __restrict__ proj_f, float* xs, int lane)
{
    constexpr int OUT = 64;
    float2 acc = *reinterpret_cast<const float2*>(sB + 2 * lane);
#pragma unroll
    for (int k = 0; k < 32; k += 4) {
        float4 xv = *reinterpret_cast<const float4*>(xs + k);
        float2 w;
        w = *reinterpret_cast<const float2*>(sW + (k    ) * OUT + 2 * lane); acc.x += xv.x * w.x; acc.y += xv.x * w.y;
        w = *reinterpret_cast<const float2*>(sW + (k + 1) * OUT + 2 * lane); acc.x += xv.y * w.x; acc.y += xv.y * w.y;
        w = *reinterpret_cast<const float2*>(sW + (k + 2) * OUT + 2 * lane); acc.x += xv.z * w.x; acc.y += xv.z * w.y;
        w = *reinterpret_cast<const float2*>(sW + (k + 3) * OUT + 2 * lane); acc.x += xv.w * w.x; acc.y += xv.w * w.y;
    }
    acc.x = fmaxf(acc.x, 0.f); acc.y = fmaxf(acc.y, 0.f);
    *reinterpret_cast<float2*>(out_f + node * OUT + 2 * lane) = acc;
    *reinterpret_cast<float2*>(xs + 64 + 2 * lane) = acc;
    __syncwarp();
    int c = lane & 15, h = lane >> 4;
    float pr = 0.f;
#pragma unroll
    for (int k = 0; k < 32; k += 4) {
        int kk = h * 32 + k;
        float4 xv = *reinterpret_cast<const float4*>(xs + 64 + kk);
        pr += xv.x * sWA[WA64X16(kk,     c)];
        pr += xv.y * sWA[WA64X16(kk + 1, c)];
        pr += xv.z * sWA[WA64X16(kk + 2, c)];
        pr += xv.w * sWA[WA64X16(kk + 3, c)];
    }
    pr += __shfl_down_sync(FULLM, pr, 16);
    if (lane < 16) proj_f[node * 16 + lane] = pr;
    __syncwarp();
}

template <bool SELF_FIRST>
__device__ __forceinline__ void layer3_node2(
    int nodeA, int nodeB, const float* __restrict__ self_f, const float* __restrict__ other_f,
    const int* __restrict__ cnt, const int* __restrict__ list,
    const float* sW, const float* sB, const float* sWA,
    float* __restrict__ out_f, float* __restrict__ proj_f,
    float* xsA, float* xsB, int lane)
{
    constexpr int IN = 16;
    constexpr int SOFF = SELF_FIRST ? 0 : IN;
    constexpr int AOFF = SELF_FIRST ? IN : 0;
#pragma unroll
    for (int k = lane; k < IN; k += 32) {
        xsA[SOFF + k] = self_f[nodeA * IN + k];
        xsB[SOFF + k] = self_f[nodeB * IN + k];
    }
    int nA = min(cnt[nodeA], CAP), nB = min(cnt[nodeB], CAP);
    float4 accA, accB; int iA0, iA1, iB0, iB1;
    gather_agg2<16>(other_f, list + nodeA * CAP, nA, list + nodeB * CAP, nB,
                    lane, accA, accB, iA0, iA1, iB0, iB1);
    int v = lane & 3, g = lane >> 2;
    if (g == 0) {
        *reinterpret_cast<float4*>(xsA + AOFF + v * 4) = accA;
        *reinterpret_cast<float4*>(xsB + AOFF + v * 4) = accB;
    }
    __syncwarp();
    l3_math(nodeA, sW, sB, sWA, out_f, proj_f, xsA, lane);
    l3_math(nodeB, sW, sB, sWA, out_f, proj_f, xsB, lane);
}

__global__ void __launch_bounds__(256) l3_k(
    const float* __restrict__ wp3, const float* __restrict__ bp3,
    const float* __restrict__ wt3, const float* __restrict__ bt3,
    const float* __restrict__ wp4, const float* __restrict__ wt4)
{
    __shared__ float sW[2048], sWA[1040], sB[64];
    __shared__ __align__(16) float sX[8][2][128];
    int tid = threadIdx.x, warp = tid >> 5, lane = tid & 31;
    int half = gridDim.x >> 1;
    bool pside = blockIdx.x < half;
    const float* W  = pside ? wp3 : wt3;
    const float* B  = pside ? bp3 : bt3;
    const float* WA = pside ? wt4 : (wp4 + 1024);
    ((float4*)sW)[tid]       = ((const float4*)W)[tid];
    ((float4*)sW)[tid + 256] = ((const float4*)W)[tid + 256];
    for (int i = tid; i < 1024; i += 256) {
        int k = i >> 4, c = i & 15;
        sWA[WA64X16(k, c)] = WA[i];
    }
    if (tid < 64) sB[tid] = B[tid];
    __syncthreads();
    int bid = pside ? blockIdx.x : blockIdx.x - half;
    int gw = bid * 8 + warp;
    if (pside) layer3_node2<true >(gw, gw + HALFN, d_pb, d_tb, d_rcnt, d_rlist, sW, sB, sWA, d_pa, d_prt, sX[warp][0], sX[warp][1], lane);
    else       layer3_node2<false>(gw, gw + HALFN, d_tb, d_pb, d_ccnt, d_clist, sW, sB, sWA, d_ta, d_prp, sX[warp][0], sX[warp][1], lane);
}

// ---------------- L4 per-node math (xs: self in [0,64), agg in [64,80)) ----------------
__device__ __forceinline__ float l4_math(
    const float* sW, const float* sB, const float* sAC, float* xs, int lane)
{
    int c = lane & 15, h = lane >> 4;
    float acc = 0.f;
#pragma unroll
    for (int k = 0; k < 32; k += 4) {
        int kk = h * 32 + k;
        float4 xv = *reinterpret_cast<const float4*>(xs + kk);
        acc += xv.x * sW[W64X16(kk,     c)];
        acc += xv.y * sW[W64X16(kk + 1, c)];
        acc += xv.z * sW[W64X16(kk + 2, c)];
        acc += xv.w * sW[W64X16(kk + 3, c)];
    }
    acc += __shfl_down_sync(FULLM, acc, 16);
    float contrib = 0.f;
    if (lane < 16) {
        float a = sB[lane] + xs[64 + lane] + acc;
        contrib = fmaxf(a, 0.f) * sAC[lane];
    }
#pragma unroll
    for (int d = 16; d > 0; d >>= 1)
        contrib += __shfl_down_sync(FULLM, contrib, d);
    return contrib;   // lane 0
}

__device__ __forceinline__ void l4_front2(
    int nodeA, int nodeB, const float* __restrict__ self_f, const float* __restrict__ proj_other,
    const int* __restrict__ cnt, const int* __restrict__ list,
    float* xsA, float* xsB, int lane,
    int& nA, int& nB, int& iA0, int& iA1, int& iB0, int& iB1)
{
#pragma unroll
    for (int k = lane; k < 64; k += 32) {
        xsA[k] = self_f[nodeA * 64 + k];
        xsB[k] = self_f[nodeB * 64 + k];
    }
    nA = min(cnt[nodeA], CAP); nB = min(cnt[nodeB], CAP);
    float4 accA, accB;
    gather_agg2<16>(proj_other, list + nodeA * CAP, nA, list + nodeB * CAP, nB,
                    lane, accA, accB, iA0, iA1, iB0, iB1);
    int v = lane & 3, g = lane >> 2;
    if (g == 0) {
        *reinterpret_cast<float4*>(xsA + 64 + v * 4) = accA;
        *reinterpret_cast<float4*>(xsB + 64 + v * 4) = accB;
    }
    __syncwarp();
}

// ---------------- L4 p-side ----------------
__global__ void __launch_bounds__(256) l4p_k(
    const float* __restrict__ wp4, const float* __restrict__ bp4,
    const float* __restrict__ wac)
{
    __shared__ float sW[1104], sB[16], sAC[16];
    __shared__ __align__(16) float sX[8][2][80];
    int tid = threadIdx.x, warp = tid >> 5, lane = tid & 31;
    for (int i = tid; i < 1024; i += 256) {
        int k = i >> 4, c = i & 15;
        sW[W64X16(k, c)] = wp4[i];
    }
    if (tid < 16) { sB[tid] = bp4[tid]; sAC[tid] = wac[tid]; }
    __syncthreads();
    int gw = blockIdx.x * 8 + warp;
    int nodeA = gw, nodeB = gw + HALFN;
    int nA, nB, iA0, iA1, iB0, iB1;
    l4_front2(nodeA, nodeB, d_pa, d_prp, d_rcnt, d_rlist, sX[warp][0], sX[warp][1], lane, nA, nB, iA0, iA1, iB0, iB1);
    float cA = l4_math(sW, sB, sAC, sX[warp][0], lane);
    float cB = l4_math(sW, sB, sAC, sX[warp][1], lane);
    if (lane == 0) { d_lp[nodeA] = cA; d_lp[nodeB] = cB; }
}

// ---------------- L4 t-side + logits + ccnt reset ----------------
__global__ void __launch_bounds__(256) l4t_logits_k(
    const float* __restrict__ wt4, const float* __restrict__ bt4,
    const float* __restrict__ wac, const float* __restrict__ bac)
{
    __shared__ float sW[1104], sB[16], sAC[16];
    __shared__ __align__(16) float sX[8][2][80];
    int tid = threadIdx.x, warp = tid >> 5, lane = tid & 31;
    for (int i = tid; i < 1024; i += 256) {
        int k = i >> 4, c = i & 15;
        sW[W64X16(k, c)] = wt4[1024 + i];   // self part (rows 64..127)
    }
    if (tid < 16) { sB[tid] = bt4[tid]; sAC[tid] = wac[16 + tid]; }
    __syncthreads();
    float bias = bac[0];
    int gw = blockIdx.x * 8 + warp;
    int nodeA = gw, nodeB = gw + HALFN;
    int nA, nB, iA0, iA1, iB0, iB1;
    l4_front2(nodeA, nodeB, d_ta, d_prt, d_ccnt, d_clist, sX[warp][0], sX[warp][1], lane, nA, nB, iA0, iA1, iB0, iB1);

    float sA = 0.f, sBv = 0.f;
    if (lane < nA) sA += d_lp[iA0];
    if (lane + 32 < nA) sA += d_lp[iA1];
    if (lane < nB) sBv += d_lp[iB0];
    if (lane + 32 < nB) sBv += d_lp[iB1];
    if (nA > 64) {
        const int* lstA = d_clist + nodeA * CAP;
        for (int e = 64 + lane; __any_sync(FULLM, e < nA); e += 32)
            if (e < nA) sA += d_lp[lstA[e]];
    }
    if (nB > 64) {
        const int* lstB = d_clist + nodeB * CAP;
        for (int e = 64 + lane; __any_sync(FULLM, e < nB); e += 32)
            if (e < nB) sBv += d_lp[lstB[e]];
    }

    float cA = l4_math(sW, sB, sAC, sX[warp][0], lane);
    float cB = l4_math(sW, sB, sAC, sX[warp][1], lane);
#pragma unroll
    for (int d = 16; d > 0; d >>= 1) {
        sA  += __shfl_down_sync(FULLM, sA, d);
        sBv += __shfl_down_sync(FULLM, sBv, d);
    }
    if (lane == 0) {
        d_logits[nodeA] = sA + cA + bias;
        d_logits[nodeB] = sBv + cB + bias;
        d_ccnt[nodeA] = 0;                  // last user of ccnt — reset for next launch
        d_ccnt[nodeB] = 0;
    }
}

// ---------------- softmax: 16 redundant blocks, each writes a 512-slice ----------------
__global__ void __launch_bounds__(512) softmax_k(float* __restrict__ out) {
    __shared__ float sm[512];
    int tid = threadIdx.x;
    float m = -1e30f;
    for (int i = tid; i < NT; i += 512) m = fmaxf(m, d_logits[i]);
    sm[tid] = m; __syncthreads();
    for (int s = 256; s > 0; s >>= 1) {
        if (tid < s) sm[tid] = fmaxf(sm[tid], sm[tid + s]);
        __syncthreads();
    }
    float mx = sm[0];
    __syncthreads();
    float s = 0.f;
    for (int i = tid; i < NT; i += 512) s += __expf(d_logits[i] - mx);
    sm[tid] = s; __syncthreads();
    for (int st = 256; st > 0; st >>= 1) {
        if (tid < st) sm[tid] += sm[tid + st];
        __syncthreads();
    }
    float inv = 1.f / sm[0];
    int base = blockIdx.x * 512;
    out[base + tid] = __expf(d_logits[base + tid] - mx) * inv;
}

// ---------------- launch ----------------
extern "C" void kernel_launch(void* const* d_in, const int* in_sizes, int n_in,
                              void* d_out, int out_size) {
    const float* p    = (const float*)d_in[0];
    const float* t    = (const float*)d_in[1];
    const float* adj  = (const float*)d_in[2];
    const float* w_p1 = (const float*)d_in[3];  const float* b_p1 = (const float*)d_in[4];
    const float* w_t1 = (const float*)d_in[5];  const float* b_t1 = (const float*)d_in[6];
    const float* w_p2 = (const float*)d_in[7];  const float* b_p2 = (const float*)d_in[8];
    const float* w_t2 = (const float*)d_in[9];  const float* b_t2 = (const float*)d_in[10];
    const float* w_p3 = (const float*)d_in[11]; const float* b_p3 = (const float*)d_in[12];
    const float* w_t3 = (const float*)d_in[13]; const float* b_t3 = (const float*)d_in[14];
    const float* w_p4 = (const float*)d_in[15]; const float* b_p4 = (const float*)d_in[16];
    const float* w_t4 = (const float*)d_in[17]; const float* b_t4 = (const float*)d_in[18];
    const float* w_ac = (const float*)d_in[19]; const float* b_ac = (const float*)d_in[20];
    float* out = (float*)d_out;

    build_k<<<NP, 256>>>(adj);
    l1_k<<<1024, 256>>>(p, t, w_p1, b_p1, w_t1, b_t1);   // 512 blocks/side, 2 nodes/warp
    l2_k<<<1024, 256>>>(w_p2, b_p2, w_t2, b_t2);
    l3_k<<<1024, 256>>>(w_p3, b_p3, w_t3, b_t3, w_p4, w_t4);
    l4p_k<<<512, 256>>>(w_p4, b_p4, w_ac);
    l4t_logits_k<<<512, 256>>>(w_t4, b_t4, w_ac, b_ac);
    softmax_k<<<16, 512>>>(out);
}